// round 17
// baseline (speedup 1.0000x reference)
#include <cuda_runtime.h>
#include <cuda_fp16.h>
#include <cstdint>
#include <math.h>

#define BB 8
#define RR 256
#define DD 128
#define NROW (BB*RR)
#define NEG 0.1f
#define SXH 136            // X row stride (halves): 272B = 17x16B (odd) -> ldmatrix conflict-free
#define SWH 136            // Wt row stride (halves): same property
#define JQ 64              // j rows per item (quarter tile)

// Persistent scratch (no allocations allowed)
__device__ float g_h[NROW*DD];
__device__ float g_ti[NROW*DD];
__device__ float g_tj[NROW*DD];
__device__ float g_mp8[8*NROW*DD];   // per-(jq,jgroup) partial mpre slabs

__device__ __forceinline__ float lrelu(float x){ return x > 0.f ? x : NEG*x; }

__device__ __forceinline__ void group_bar(int id){
    asm volatile("bar.sync %0, %1;" :: "r"(id), "r"(128) : "memory");
}
__device__ __forceinline__ uint32_t smem_u32(const void* p){
    return (uint32_t)__cvta_generic_to_shared(p);
}
__device__ __forceinline__ void ldsm_x4(uint32_t& r0, uint32_t& r1, uint32_t& r2, uint32_t& r3,
                                        uint32_t addr){
    asm volatile("ldmatrix.sync.aligned.m8n8.x4.shared.b16 {%0,%1,%2,%3}, [%4];"
        : "=r"(r0), "=r"(r1), "=r"(r2), "=r"(r3) : "r"(addr));
}

// ---------------------------------------------------------------------------
// F1: fused embed + titj.  8 rows/block, 256 threads = 128 cols x 2 halves.
// ---------------------------------------------------------------------------
__global__ void __launch_bounds__(256)
k_embed_titj(const float* __restrict__ fres, const float* __restrict__ Wemb,
             const float* __restrict__ We1, const float* __restrict__ be1)
{
    __shared__ float sF[8][20];
    __shared__ float sH[8][DD];
    const int r0 = blockIdx.x*8;
    const int t = threadIdx.x, c = t & 127, half = t >> 7;

    for (int idx = t; idx < 8*20; idx += 256)
        sF[idx/20][idx%20] = fres[(size_t)(r0 + idx/20)*20 + idx%20];
    __syncthreads();

    {   // embed: 4 rows per thread
        float a[4] = {0,0,0,0};
        #pragma unroll
        for (int k = 0; k < 20; k++){
            float wv = Wemb[k*DD + c];
            #pragma unroll
            for (int i = 0; i < 4; i++) a[i] += sF[half*4+i][k]*wv;
        }
        #pragma unroll
        for (int i = 0; i < 4; i++){
            float hv = lrelu(a[i]);
            sH[half*4+i][c] = hv;
            g_h[(size_t)(r0+half*4+i)*DD + c] = hv;
        }
    }
    __syncthreads();

    {   // titj: 8 rows per thread; half 0 -> ti, half 1 -> tj
        const float* W = We1 + (size_t)half*DD*DD;
        float a[8] = {0,0,0,0,0,0,0,0};
        #pragma unroll 4
        for (int k = 0; k < DD; k++){
            float wv = W[(size_t)k*DD + c];
            #pragma unroll
            for (int r = 0; r < 8; r++) a[r] += sH[r][k]*wv;
        }
        if (half == 0){
            const float be = be1[c];
            #pragma unroll
            for (int r = 0; r < 8; r++) g_ti[(size_t)(r0+r)*DD + c] = a[r] + be;
        } else {
            #pragma unroll
            for (int r = 0; r < 8; r++) g_tj[(size_t)(r0+r)*DD + c] = a[r];
        }
    }
}

// ---------------------------------------------------------------------------
// F2: fused node update (u1,u2) + titj for the next iteration.  8 rows/block.
// ---------------------------------------------------------------------------
__global__ void __launch_bounds__(256)
k_node_titj(const float* __restrict__ Wh1, const float* __restrict__ bh1,
            const float* __restrict__ Wh2, const float* __restrict__ bh2,
            const float* __restrict__ We1, const float* __restrict__ be1)
{
    __shared__ float sHM[8][2*DD];   // [h | mpre]
    __shared__ float sU[8][DD];
    __shared__ float sHN[8][DD];
    const int r0 = blockIdx.x*8;
    const int t = threadIdx.x, c = t & 127, half = t >> 7;

    for (int idx = t; idx < 8*DD; idx += 256){
        int r = idx >> 7, cc = idx & 127;
        sHM[r][cc] = g_h[(size_t)(r0+r)*DD + cc];
        float mp = 0.f;
        #pragma unroll
        for (int s = 0; s < 8; s++)
            mp += g_mp8[((size_t)s*NROW + (r0+r))*DD + cc];
        sHM[r][DD + cc] = mp;
    }
    __syncthreads();

    {   // u1: 4 rows per thread, K=256
        float a[4] = {0,0,0,0};
        #pragma unroll 4
        for (int k = 0; k < 2*DD; k++){
            float wv = Wh1[(size_t)k*DD + c];
            #pragma unroll
            for (int i = 0; i < 4; i++) a[i] += sHM[half*4+i][k]*wv;
        }
        const float b1 = bh1[c];
        #pragma unroll
        for (int i = 0; i < 4; i++) sU[half*4+i][c] = lrelu(a[i] + b1);
    }
    __syncthreads();

    {   // u2 + residual: 4 rows per thread
        float a[4] = {0,0,0,0};
        #pragma unroll 4
        for (int k = 0; k < DD; k++){
            float wv = Wh2[(size_t)k*DD + c];
            #pragma unroll
            for (int i = 0; i < 4; i++) a[i] += sU[half*4+i][k]*wv;
        }
        const float b2 = bh2[c];
        #pragma unroll
        for (int i = 0; i < 4; i++){
            float hn = a[i] + b2 + sHM[half*4+i][c];
            sHN[half*4+i][c] = hn;
            g_h[(size_t)(r0+half*4+i)*DD + c] = hn;
        }
    }
    __syncthreads();

    {   // titj on updated h: 8 rows per thread
        const float* W = We1 + (size_t)half*DD*DD;
        float a[8] = {0,0,0,0,0,0,0,0};
        #pragma unroll 4
        for (int k = 0; k < DD; k++){
            float wv = W[(size_t)k*DD + c];
            #pragma unroll
            for (int r = 0; r < 8; r++) a[r] += sHN[r][k]*wv;
        }
        if (half == 0){
            const float be = be1[c];
            #pragma unroll
            for (int r = 0; r < 8; r++) g_ti[(size_t)(r0+r)*DD + c] = a[r] + be;
        } else {
            #pragma unroll
            for (int r = 0; r < 8; r++) g_tj[(size_t)(r0+r)*DD + c] = a[r];
        }
    }
}

// ---------------------------------------------------------------------------
// F3: final node update -> out.  8 rows/block.
// ---------------------------------------------------------------------------
__global__ void __launch_bounds__(256)
k_node_out(const float* __restrict__ Wh1, const float* __restrict__ bh1,
           const float* __restrict__ Wh2, const float* __restrict__ bh2,
           float* __restrict__ out)
{
    __shared__ float sHM[8][2*DD];
    __shared__ float sU[8][DD];
    const int r0 = blockIdx.x*8;
    const int t = threadIdx.x, c = t & 127, half = t >> 7;

    for (int idx = t; idx < 8*DD; idx += 256){
        int r = idx >> 7, cc = idx & 127;
        sHM[r][cc] = g_h[(size_t)(r0+r)*DD + cc];
        float mp = 0.f;
        #pragma unroll
        for (int s = 0; s < 8; s++)
            mp += g_mp8[((size_t)s*NROW + (r0+r))*DD + cc];
        sHM[r][DD + cc] = mp;
    }
    __syncthreads();
    float a[4] = {0,0,0,0};
    #pragma unroll 4
    for (int k = 0; k < 2*DD; k++){
        float wv = Wh1[(size_t)k*DD + c];
        #pragma unroll
        for (int i = 0; i < 4; i++) a[i] += sHM[half*4+i][k]*wv;
    }
    const float b1 = bh1[c];
    #pragma unroll
    for (int i = 0; i < 4; i++) sU[half*4+i][c] = lrelu(a[i] + b1);
    __syncthreads();
    float a2[4] = {0,0,0,0};
    #pragma unroll 4
    for (int k = 0; k < DD; k++){
        float wv = Wh2[(size_t)k*DD + c];
        #pragma unroll
        for (int i = 0; i < 4; i++) a2[i] += sU[half*4+i][k]*wv;
    }
    const float b2 = bh2[c];
    #pragma unroll
    for (int i = 0; i < 4; i++)
        out[(size_t)(r0+half*4+i)*DD + c] = a2[i] + b2 + sHM[half*4+i][c];
}

// ---------------------------------------------------------------------------
// K4: edge kernel — fp16 m16n8k16, B (W_e2) resident in REGISTERS.
// 256 threads/CTA, 2 CTAs/SM.  8 warps = 2 j-groups x 4 c-groups,
// warp tile 32j x 32c.  Item = (tile, jq) = 64 j-rows.
// B fragments (64 regs/thread) preloaded once; mainloop = 2 LDSM + 8 MMA.
// ---------------------------------------------------------------------------
__global__ void __launch_bounds__(256, 2)
k_edge(const float* __restrict__ be2,
       const float* __restrict__ Winf,
       const float* __restrict__ binf,
       const float* __restrict__ We1,
       const float* __restrict__ We2,
       const float* __restrict__ coords,
       int nitems)
{
    extern __shared__ char smraw[];
    __half* sWt  = (__half*)smraw;                  // 34816 B staging (dead after preload)
    __half* sXh  = (__half*)smraw;                  // overlays sWt: 64*SXH*2 = 17408 B
    float* sCall = (float*)(smraw + 34816);         // 24576 B  all-batch coords
    float* sEp = sCall + BB*3*RR;                   // 64
    float* sE  = sEp + JQ;                          // 64
    float* sWd = sE  + JQ;                          // 128
    float* sBc = sWd + DD;                          // 128
    float* sWc = sBc + DD;                          // 128

    const int t    = threadIdx.x;
    const int w    = t >> 5;
    const int lane = t & 31;
    const int g    = lane >> 2;
    const int tig  = lane & 3;
    const int cg   = w & 3;             // c-group 0..3
    const int jg   = w >> 2;            // j-group 0..1
    const int cbase = cg * 32;
    const int jbl  = jg * 32;           // local j base of this warp's A tile
    const int barid = 1 + jg;           // 128-thread group barriers

    // one-time staging: W_e2 transposed [c][k] halves, coords, small vectors
    for (int idx = t; idx < DD*DD; idx += 256) {
        int k = idx >> 7, c = idx & 127;
        sWt[c*SWH + k] = __float2half_rn(We2[idx]);
    }
    for (int idx = t; idx < BB*RR; idx += 256) {
        int b = idx >> 8, j = idx & 255;
        const float* cp = coords + (size_t)idx*3;
        sCall[b*768 + j]        = cp[0];
        sCall[b*768 + 256 + j]  = cp[1];
        sCall[b*768 + 512 + j]  = cp[2];
    }
    if (t < DD) {
        sWd[t] = We1[2*DD*DD + t];
        sBc[t] = be2[t];
        sWc[t] = Winf[t];
    }
    const float bi = binf[0];
    __syncthreads();

    // ---- preload ALL B fragments into registers (constant across items) ----
    uint32_t Bf[8][4][2];
    {
        uint32_t bAddr[2];
        #pragma unroll
        for (int nb = 0; nb < 2; nb++)
            bAddr[nb] = smem_u32(&sWt[(size_t)(cbase + nb*16 + ((lane >> 4) << 3)
                                               + (lane & 7))*SWH
                                      + (((lane >> 3) & 1) << 3)]);
        #pragma unroll
        for (int ks = 0; ks < 8; ks++)
            #pragma unroll
            for (int nb = 0; nb < 2; nb++)
                ldsm_x4(Bf[ks][nb*2][0], Bf[ks][nb*2][1],
                        Bf[ks][nb*2+1][0], Bf[ks][nb*2+1][1],
                        bAddr[nb] + (uint32_t)ks*32);
    }
    __syncthreads();   // sWt reads done; region becomes sXh

    // A ldmatrix per-lane base addresses (fixed across items)
    uint32_t aAddr[2];
    #pragma unroll
    for (int mi = 0; mi < 2; mi++)
        aAddr[mi] = smem_u32(&sXh[(size_t)(jbl + mi*16 + (lane & 15))*SXH
                                  + ((lane >> 4) << 3)]);

    const int k4 = lane*4;
    const float4 wdv = *(const float4*)&sWd[k4];

    for (int item = blockIdx.x; item < nitems; item += gridDim.x) {
        const int tile = item >> 2, jq = item & 3;
        const int b = tile >> 8, i = tile & 255;
        const int jg0 = jq * JQ;        // global j offset of this item
        const float* sC = sCall + b*768;

        // per-thread ti load (all warps hit same 4 lines -> L1)
        const float4 tiv = *(const float4*)&g_ti[(size_t)tile*DD + k4];

        // ---- build own 8 local X rows as fp16 (warp w builds [w*8, w*8+8)) ----
        {
            const float* tjb = g_tj + (size_t)b*RR*DD;
            const float cix = sC[i], ciy = sC[256 + i], ciz = sC[512 + i];
            const int jw = w * 8;
            #pragma unroll
            for (int jj = 0; jj < 8; jj += 2) {
                const int jl = jw + jj, jl1 = jw + jj + 1;
                const int jA = jg0 + jl, jB = jg0 + jl1;   // global
                float4 tv0 = *(const float4*)&tjb[(size_t)jA*DD + k4];
                float4 tv1 = *(const float4*)&tjb[(size_t)jB*DD + k4];
                float dx0 = sC[jA] - cix, dy0 = sC[256+jA] - ciy, dz0 = sC[512+jA] - ciz;
                float dx1 = sC[jB] - cix, dy1 = sC[256+jB] - ciy, dz1 = sC[512+jB] - ciz;
                float d20 = dx0*dx0 + dy0*dy0 + dz0*dz0;
                float d21 = dx1*dx1 + dy1*dy1 + dz1*dz1;
                __half2 h01 = __floats2half2_rn(lrelu(tiv.x + tv0.x + d20*wdv.x),
                                                lrelu(tiv.y + tv0.y + d20*wdv.y));
                __half2 h23 = __floats2half2_rn(lrelu(tiv.z + tv0.z + d20*wdv.z),
                                                lrelu(tiv.w + tv0.w + d20*wdv.w));
                uint2 u0; u0.x = *(uint32_t*)&h01; u0.y = *(uint32_t*)&h23;
                *(uint2*)&sXh[(size_t)jl*SXH + k4] = u0;
                __half2 h45 = __floats2half2_rn(lrelu(tiv.x + tv1.x + d21*wdv.x),
                                                lrelu(tiv.y + tv1.y + d21*wdv.y));
                __half2 h67 = __floats2half2_rn(lrelu(tiv.z + tv1.z + d21*wdv.z),
                                                lrelu(tiv.w + tv1.w + d21*wdv.w));
                uint2 u1; u1.x = *(uint32_t*)&h45; u1.y = *(uint32_t*)&h67;
                *(uint2*)&sXh[(size_t)jl1*SXH + k4] = u1;
            }
        }
        if (cg == 0) sEp[jbl + lane] = 0.f;     // zero own group's logit slots
        group_bar(barid);

        // ---- mainloop: 32x32 warp tile, 2 LDSM + 8 MMA per k-step ----
        float acc[2][4][4];
        #pragma unroll
        for (int mi = 0; mi < 2; mi++)
            #pragma unroll
            for (int ni = 0; ni < 4; ni++)
                #pragma unroll
                for (int q = 0; q < 4; q++) acc[mi][ni][q] = 0.f;

        #pragma unroll
        for (int ks = 0; ks < 8; ks++) {
            uint32_t A[2][4];
            #pragma unroll
            for (int mi = 0; mi < 2; mi++)
                ldsm_x4(A[mi][0], A[mi][1], A[mi][2], A[mi][3],
                        aAddr[mi] + (uint32_t)ks*32);
            #pragma unroll
            for (int mi = 0; mi < 2; mi++)
                #pragma unroll
                for (int ni = 0; ni < 4; ni++)
                    asm volatile(
                        "mma.sync.aligned.m16n8k16.row.col.f32.f16.f16.f32 "
                        "{%0,%1,%2,%3}, {%4,%5,%6,%7}, {%8,%9}, {%0,%1,%2,%3};"
                        : "+f"(acc[mi][ni][0]), "+f"(acc[mi][ni][1]),
                          "+f"(acc[mi][ni][2]), "+f"(acc[mi][ni][3])
                        : "r"(A[mi][0]), "r"(A[mi][1]), "r"(A[mi][2]), "r"(A[mi][3]),
                          "r"(Bf[ks][ni][0]), "r"(Bf[ks][ni][1]));
        }

        // ---- epilogue: m in place, gate, masked j-reduction ----
        float bc[8], wc[8];
        #pragma unroll
        for (int ni = 0; ni < 4; ni++)
            #pragma unroll
            for (int q = 0; q < 2; q++) {
                int c = cbase + ni*8 + tig*2 + q;
                bc[ni*2+q] = sBc[c];
                wc[ni*2+q] = sWc[c];
            }
        #pragma unroll
        for (int mi = 0; mi < 2; mi++)
            #pragma unroll
            for (int ni = 0; ni < 4; ni++)
                #pragma unroll
                for (int q4 = 0; q4 < 4; q4++)
                    acc[mi][ni][q4] = lrelu(acc[mi][ni][q4] + bc[ni*2 + (q4 & 1)]);

        // pass 1: per-j gate logit partials (32 c per warp, 4 warps per group)
        #pragma unroll
        for (int mi = 0; mi < 2; mi++)
            #pragma unroll
            for (int r = 0; r < 2; r++) {
                float p = 0.f;
                #pragma unroll
                for (int ni = 0; ni < 4; ni++)
                    #pragma unroll
                    for (int q = 0; q < 2; q++)
                        p += acc[mi][ni][r*2+q] * wc[ni*2+q];
                p += __shfl_xor_sync(0xffffffffu, p, 1);
                p += __shfl_xor_sync(0xffffffffu, p, 2);
                if (tig == 0) atomicAdd(&sEp[jbl + mi*16 + g + r*8], p);
            }
        group_bar(barid);
        if (cg == 0) {
            int jl = jbl + lane;
            float s = sEp[jl] + bi;
            sE[jl] = ((jg0 + jl) == i) ? 0.f : __fdividef(1.f, 1.f + __expf(-s));
        }
        group_bar(barid);

        // pass 2: mpre[c] partial = sum over group's 32 j's -> per-group slab
        float macc[8];
        #pragma unroll
        for (int q = 0; q < 8; q++) macc[q] = 0.f;
        #pragma unroll
        for (int mi = 0; mi < 2; mi++)
            #pragma unroll
            for (int r = 0; r < 2; r++) {
                float e = sE[jbl + mi*16 + g + r*8];
                #pragma unroll
                for (int ni = 0; ni < 4; ni++)
                    #pragma unroll
                    for (int q = 0; q < 2; q++)
                        macc[ni*2+q] += acc[mi][ni][r*2+q] * e;
            }
        #pragma unroll
        for (int q = 0; q < 8; q++) {
            macc[q] += __shfl_xor_sync(0xffffffffu, macc[q], 4);
            macc[q] += __shfl_xor_sync(0xffffffffu, macc[q], 8);
            macc[q] += __shfl_xor_sync(0xffffffffu, macc[q], 16);
        }
        if (g == 0) {
            float* slab = g_mp8 + ((size_t)(jq*2 + jg)*NROW + tile)*DD;
            #pragma unroll
            for (int q = 0; q < 8; q++)
                slab[cbase + (q >> 1)*8 + tig*2 + (q & 1)] = macc[q];
        }
    }
}

// ---------------------------------------------------------------------------
extern "C" void kernel_launch(void* const* d_in, const int* in_sizes, int n_in,
                              void* d_out, int out_size)
{
    const float* fres   = (const float*)d_in[0];
    const float* coords = (const float*)d_in[1];
    const float* Wemb   = (const float*)d_in[2];
    const float* We1    = (const float*)d_in[3];
    const float* be1    = (const float*)d_in[4];
    const float* We2    = (const float*)d_in[5];
    const float* be2    = (const float*)d_in[6];
    const float* Winf   = (const float*)d_in[7];
    const float* binf   = (const float*)d_in[8];
    const float* Wh1    = (const float*)d_in[9];
    const float* bh1    = (const float*)d_in[10];
    const float* Wh2    = (const float*)d_in[11];
    const float* bh2    = (const float*)d_in[12];
    float* out = (float*)d_out;

    const int EDGE_SMEM = 34816 + (BB*3*RR + 2*JQ + 3*DD)*(int)sizeof(float);  // 61440
    cudaFuncSetAttribute(k_edge, cudaFuncAttributeMaxDynamicSharedMemorySize, EDGE_SMEM);

    k_embed_titj<<<NROW/8, 256>>>(fres, Wemb, We1, be1);
    k_edge<<<296, 256, EDGE_SMEM>>>(be2, Winf, binf, We1, We2, coords, NROW*4);
    k_node_titj<<<NROW/8, 256>>>(Wh1, bh1, Wh2, bh2, We1, be1);
    k_edge<<<296, 256, EDGE_SMEM>>>(be2, Winf, binf, We1, We2, coords, NROW*4);
    k_node_out<<<NROW/8, 256>>>(Wh1, bh1, Wh2, bh2, out);
}